// round 9
// baseline (speedup 1.0000x reference)
#include <cuda_runtime.h>
#include <stdint.h>

#define H   768
#define NN  32
#define KK  32
#define TT  128
#define NEGINF -1e20f

// ---- output layout (concatenated, float32) ----
// score:            [0,        1024)
// shifted_encoded:  [1024,     3146752)   32*128*768
// shifted_mask:     [3146752,  3150848)   32*128
// shifted_use:      [3150848,  3175424)   32*768
// shifted_index:    [3175424,  3179520)   32*128
#define OFF_SCORE 0
#define OFF_ENC   1024
#define OFF_MASK  3146752
#define OFF_USE   3150848
#define OFF_IDX   3175424

// ---- scratch (device globals; no allocation allowed) ----
#define GSPLIT 32
#define GCHUNK (H / GSPLIT)       // 24
__device__ float g_cqk_pro[NN * H];
__device__ float g_vpart[GSPLIT][NN * H];
__device__ float g_v[NN * H];
__device__ float g_c[NN];

// ============================================================
// K1: cqk_pro[n,h] = sum_j cqk[n,j] * W_cqk[h,j] + b_cqk[h]
//     cqk[n,j] = j<H ? ctx[n,2,j] : tracked[n,j-H]
// warp-per-h, all 32 n accumulated per lane; cqk chunk in smem.
// grid: 96 blocks x 256 threads (8 warps -> 8 h per block)
// ============================================================
#define K1_CHUNK 256
__global__ void k1_cqk_pro(const float* __restrict__ ctx,
                           const float* __restrict__ tracked,
                           const float* __restrict__ Wcqk,
                           const float* __restrict__ bcqk) {
    __shared__ float s[NN][K1_CHUNK];
    const int tid  = threadIdx.x;
    const int lane = tid & 31;
    const int wid  = tid >> 5;
    const int h    = blockIdx.x * 8 + wid;

    float acc[NN];
#pragma unroll
    for (int n = 0; n < NN; n++) acc[n] = 0.f;

    for (int c0 = 0; c0 < 2 * H; c0 += K1_CHUNK) {
        __syncthreads();
        for (int idx = tid; idx < NN * K1_CHUNK; idx += 256) {
            int n  = idx / K1_CHUNK;
            int jj = idx - n * K1_CHUNK;
            int j  = c0 + jj;
            s[n][jj] = (j < H) ? ctx[n * 3 * H + 2 * H + j]
                               : tracked[n * H + (j - H)];
        }
        __syncthreads();
        const float* wrow = Wcqk + (size_t)h * (2 * H) + c0;
        for (int jj = lane; jj < K1_CHUNK; jj += 32) {
            float w = wrow[jj];
#pragma unroll
            for (int n = 0; n < NN; n++) acc[n] += w * s[n][jj];
        }
    }
#pragma unroll
    for (int n = 0; n < NN; n++) {
        float v = acc[n];
#pragma unroll
        for (int o = 16; o > 0; o >>= 1) v += __shfl_xor_sync(0xffffffffu, v, o);
        if (lane == n) g_cqk_pro[n * H + h] = v + bcqk[h];
    }
}

// ============================================================
// K2: v[n,h] = sum_g cqk_pro[n,g] * W_k[g,h]   (partials over g-chunks)
// thread-per-h, 32-n accumulators; W_k rows read coalesced once.
// grid: (3, GSPLIT) x 256 threads
// ============================================================
__global__ void k2_vpart(const float* __restrict__ Wk) {
    __shared__ float s[NN][GCHUNK];
    const int tid = threadIdx.x;
    const int h   = blockIdx.x * 256 + tid;
    const int g0  = blockIdx.y * GCHUNK;

    for (int idx = tid; idx < NN * GCHUNK; idx += 256) {
        int n  = idx / GCHUNK;
        int gg = idx - n * GCHUNK;
        s[n][gg] = g_cqk_pro[n * H + g0 + gg];
    }
    __syncthreads();

    float acc[NN];
#pragma unroll
    for (int n = 0; n < NN; n++) acc[n] = 0.f;
#pragma unroll
    for (int gg = 0; gg < GCHUNK; gg++) {
        float w = Wk[(size_t)(g0 + gg) * H + h];
#pragma unroll
        for (int n = 0; n < NN; n++) acc[n] += s[n][gg] * w;
    }
#pragma unroll
    for (int n = 0; n < NN; n++) g_vpart[blockIdx.y][n * H + h] = acc[n];
}

// ============================================================
// K3: reduce v partials; tail blocks compute c[n] = b_k . cqk_pro[n]
// grid: 100 blocks x 256 threads (96 reduce, 4 compute c)
// ============================================================
__global__ void k3_reduce(const float* __restrict__ bk) {
    if (blockIdx.x < 96) {
        int idx = blockIdx.x * 256 + threadIdx.x;   // 0..24575
        float sum = 0.f;
#pragma unroll
        for (int p = 0; p < GSPLIT; p++) sum += g_vpart[p][idx];
        g_v[idx] = sum;
    } else {
        int lane = threadIdx.x & 31;
        int wid  = threadIdx.x >> 5;
        int n    = (blockIdx.x - 96) * 8 + wid;     // 0..31
        float a = 0.f;
        for (int g = lane; g < H; g += 32) a += bk[g] * g_cqk_pro[n * H + g];
#pragma unroll
        for (int o = 16; o > 0; o >>= 1) a += __shfl_xor_sync(0xffffffffu, a, o);
        if (lane == 0) g_c[n] = a;
    }
}

// ============================================================
// K4: score[n,k] = mask ? sum_h P1[n,k,h]*v[n,h] + c[n] : NEGINF
// ck_mask stored as 4-byte elements (bool widened by harness);
// nonzero word == true for both int32(1) and float32(1.0).
// warp per (n,k). grid: 128 x 256
// ============================================================
__global__ void k4_score(const float* __restrict__ P1,
                         const int* __restrict__ ckmask,
                         float* __restrict__ out) {
    int w    = (blockIdx.x * 256 + threadIdx.x) >> 5;   // 0..1023
    int lane = threadIdx.x & 31;
    int n = w >> 5, k = w & 31;
    const float* p = P1 + (size_t)(n * KK + k) * H;
    const float* v = g_v + n * H;
    float a = 0.f;
#pragma unroll 4
    for (int hh = lane; hh < H; hh += 32) a += p[hh] * v[hh];
#pragma unroll
    for (int o = 16; o > 0; o >>= 1) a += __shfl_xor_sync(0xffffffffu, a, o);
    if (lane == 0)
        out[OFF_SCORE + n * KK + k] =
            (ckmask[n * KK + k] != 0) ? (a + g_c[n]) : NEGINF;
}

// ============================================================
// K5: big gather (HBM-bound): shifted_encoded = pool0[n, label[n]]
// float4 copy, 786432 vec4 elements. grid: 3072 x 256
// ============================================================
__global__ void k5_gather_enc(const float4* __restrict__ p0,
                              const int* __restrict__ label,
                              float4* __restrict__ outE) {
    int i = blockIdx.x * 256 + threadIdx.x;     // < 786432
    int n   = i / 24576;                        // 24576 = T*H/4
    int off = i - n * 24576;
    outE[i] = p0[(size_t)(n * KK + label[n]) * 24576 + off];
}

// ============================================================
// K6: small gathered outputs (mask, use, index) as float
// pool_mask also 4-byte elements; nonzero word == true.
// 4096 + 24576 + 4096 = 32768 elements. grid: 128 x 256
// ============================================================
__global__ void k6_small(const int* __restrict__ pmask,
                         const float* __restrict__ p1,
                         const int* __restrict__ ptok,
                         const int* __restrict__ label,
                         float* __restrict__ out) {
    int i = blockIdx.x * 256 + threadIdx.x;
    if (i < 4096) {
        int n = i >> 7, t = i & 127;
        out[OFF_MASK + i] =
            (pmask[(n * KK + label[n]) * TT + t] != 0) ? 1.f : 0.f;
    } else if (i < 4096 + 24576) {
        int j = i - 4096;
        int n = j / H, h2 = j - n * H;
        out[OFF_USE + j] = p1[(size_t)(n * KK + label[n]) * H + h2];
    } else {
        int j = i - 4096 - 24576;
        int n = j >> 7, t = j & 127;
        out[OFF_IDX + j] = (float)ptok[(n * KK + label[n]) * TT + t];
    }
}

extern "C" void kernel_launch(void* const* d_in, const int* in_sizes, int n_in,
                              void* d_out, int out_size) {
    const float* ctx     = (const float*)d_in[0];   // (32,3,768)
    const float* tracked = (const float*)d_in[1];   // (32,768)
    const float* pool0   = (const float*)d_in[2];   // (32,32,128,768)
    const float* pool1   = (const float*)d_in[3];   // (32,32,768)
    const int*   pmask   = (const int*)d_in[4];     // (32,32,128) bool->4B
    const int*   ckmask  = (const int*)d_in[5];     // (32,32)     bool->4B
    const int*   label   = (const int*)d_in[6];     // (32,)
    const int*   ptok    = (const int*)d_in[7];     // (32,32,128)
    const float* Wcqk    = (const float*)d_in[8];   // (768,1536)
    const float* bcqk    = (const float*)d_in[9];   // (768,)
    const float* Wk      = (const float*)d_in[10];  // (768,768)
    const float* bk      = (const float*)d_in[11];  // (768,)
    float* out = (float*)d_out;

    k1_cqk_pro<<<96, 256>>>(ctx, tracked, Wcqk, bcqk);
    k2_vpart<<<dim3(3, GSPLIT), 256>>>(Wk);
    k3_reduce<<<100, 256>>>(bk);
    k4_score<<<128, 256>>>(pool1, ckmask, out);
    k5_gather_enc<<<3072, 256>>>((const float4*)pool0, label,
                                 (float4*)(out + OFF_ENC));
    k6_small<<<128, 256>>>(pmask, pool1, ptok, label, out);
}

// round 13
// speedup vs baseline: 1.4055x; 1.4055x over previous
#include <cuda_runtime.h>
#include <stdint.h>

#define H    768
#define NN   32
#define KK   32
#define TT   128
#define NEGINF -1e20f

#define GRID 132
#define THREADS 256

// ---- output layout (concatenated, float32) ----
#define OFF_SCORE 0
#define OFF_ENC   1024
#define OFF_MASK  3146752
#define OFF_USE   3150848
#define OFF_IDX   3175424

// ---- v-GEMV split ----
#define GSPLIT 16
#define GCHUNK (H / GSPLIT)       // 48

// ---- gather partition (float4 units, total 786432) ----
#define ENC_F4 786432
#define R1_LO 0
#define R1_HI 110592              // phase1: blocks 96..131 (9216 thr x 12)
#define R2_LO 110592
#define R2_HI 368640              // phase2: blocks 48..131 (21504 thr x 12)
#define R3_LO 368640
#define R3_HI 634880              // phase3: blocks 28..131 (26624 thr x 10)
#define R4_LO 634880
#define R4_HI 667648              // phase4: blocks 128..131 (1024 thr x 32)
#define R5_LO 667648
#define R5_HI ENC_F4              // post: all threads, stride loop

// ---- scratch ----
__device__ float g_cqk_pro[NN * H];
__device__ float g_vpart[GSPLIT][NN * H];
__device__ float g_v[NN * H];
__device__ float g_c[NN];
__device__ unsigned int g_count = 0;
__device__ unsigned int g_sense = 0;

__device__ __forceinline__ void grid_barrier(unsigned int& local_sense) {
    __syncthreads();
    if (threadIdx.x == 0) {
        unsigned int next = local_sense ^ 1u;
        __threadfence();
        unsigned int old = atomicAdd(&g_count, 1u);
        if (old == GRID - 1) {
            atomicExch(&g_count, 0u);
            __threadfence();
            atomicExch(&g_sense, next);
        } else {
            while (*((volatile unsigned int*)&g_sense) != next) { }
        }
    }
    local_sense ^= 1u;
    __syncthreads();
}

// gather a contiguous float4 range [lo,hi), nthr participating threads
__device__ __forceinline__ void gather_range(const float4* __restrict__ p0,
                                             const int* __restrict__ label,
                                             float4* __restrict__ outE,
                                             int lo, int hi,
                                             int my, int nthr) {
    for (int i = lo + my; i < hi; i += nthr) {
        int n   = i / 24576;                 // T*H/4
        int off = i - n * 24576;
        outE[i] = p0[(size_t)(n * KK + label[n]) * 24576 + off];
    }
}

__global__ __launch_bounds__(THREADS, 1)
void fused_kernel(const float* __restrict__ ctx,
                  const float* __restrict__ tracked,
                  const float* __restrict__ pool0,
                  const float* __restrict__ pool1,
                  const int*   __restrict__ pmask,
                  const int*   __restrict__ ckmask,
                  const int*   __restrict__ label,
                  const int*   __restrict__ ptok,
                  const float* __restrict__ Wcqk,
                  const float* __restrict__ bcqk,
                  const float* __restrict__ Wk,
                  const float* __restrict__ bk,
                  float* __restrict__ out) {
    __shared__ float sm[NN * 256];           // 32 KB, reused per phase

    const int b    = blockIdx.x;
    const int tid  = threadIdx.x;
    const int lane = tid & 31;
    const int wid  = tid >> 5;

    unsigned int local_sense = *((volatile unsigned int*)&g_sense);

    const float4* p0f4  = (const float4*)pool0;
    float4*       outE4 = (float4*)(out + OFF_ENC);

    // ================= PHASE 1 =================
    // blocks 0..95: cqk_pro[n,h] (warp per h, smem-staged cqk chunk)
    // blocks 96..131: gather slice R1
    if (b < 96) {
        const int h = b * 8 + wid;
        float acc[NN];
#pragma unroll
        for (int n = 0; n < NN; n++) acc[n] = 0.f;

        for (int c0 = 0; c0 < 2 * H; c0 += 256) {
            __syncthreads();
            for (int idx = tid; idx < NN * 256; idx += THREADS) {
                int n  = idx >> 8;
                int jj = idx & 255;
                int j  = c0 + jj;
                sm[idx] = (j < H) ? ctx[n * 3 * H + 2 * H + j]
                                  : tracked[n * H + (j - H)];
            }
            __syncthreads();
            const float* wrow = Wcqk + (size_t)h * (2 * H) + c0;
            for (int jj = lane; jj < 256; jj += 32) {
                float w = wrow[jj];
#pragma unroll
                for (int n = 0; n < NN; n++) acc[n] += w * sm[n * 256 + jj];
            }
        }
#pragma unroll
        for (int n = 0; n < NN; n++) {
            float v = acc[n];
#pragma unroll
            for (int o = 16; o > 0; o >>= 1) v += __shfl_xor_sync(0xffffffffu, v, o);
            if (lane == n) g_cqk_pro[n * H + h] = v + bcqk[h];
        }
    } else {
        gather_range(p0f4, label, outE4, R1_LO, R1_HI,
                     (b - 96) * THREADS + tid, 36 * THREADS);
    }

    grid_barrier(local_sense);

    // ================= PHASE 2 =================
    // blocks 0..47: v partials (thread per h, g-chunk per block triple)
    // blocks 48..131: gather slice R2
    if (b < 48) {
        const int chunk = b / 3;
        const int h     = (b % 3) * 256 + tid;
        const int g0    = chunk * GCHUNK;

        for (int idx = tid; idx < NN * GCHUNK; idx += THREADS) {
            int n  = idx / GCHUNK;
            int gg = idx - n * GCHUNK;
            sm[idx] = g_cqk_pro[n * H + g0 + gg];
        }
        __syncthreads();

        float acc[NN];
#pragma unroll
        for (int n = 0; n < NN; n++) acc[n] = 0.f;
#pragma unroll 4
        for (int gg = 0; gg < GCHUNK; gg++) {
            float w = Wk[(size_t)(g0 + gg) * H + h];
#pragma unroll
            for (int n = 0; n < NN; n++) acc[n] += sm[n * GCHUNK + gg] * w;
        }
#pragma unroll
        for (int n = 0; n < NN; n++) g_vpart[chunk][n * H + h] = acc[n];
    } else {
        gather_range(p0f4, label, outE4, R2_LO, R2_HI,
                     (b - 48) * THREADS + tid, 84 * THREADS);
    }

    grid_barrier(local_sense);

    // ================= PHASE 3 =================
    // blocks 0..23: reduce v partials; 24..27: c[n]; 28..131: gather R3
    if (b < 24) {
        int id = b * THREADS + tid;                 // < 6144
#pragma unroll
        for (int k = 0; k < 4; k++) {
            int idx = id + k * 6144;                // < 24576
            float s = 0.f;
#pragma unroll
            for (int p = 0; p < GSPLIT; p++) s += g_vpart[p][idx];
            g_v[idx] = s;
        }
    } else if (b < 28) {
        int n = (b - 24) * 8 + wid;                 // 0..31
        float a = 0.f;
        for (int g = lane; g < H; g += 32) a += bk[g] * g_cqk_pro[n * H + g];
#pragma unroll
        for (int o = 16; o > 0; o >>= 1) a += __shfl_xor_sync(0xffffffffu, a, o);
        if (lane == 0) g_c[n] = a;
    } else {
        gather_range(p0f4, label, outE4, R3_LO, R3_HI,
                     (b - 28) * THREADS + tid, 104 * THREADS);
    }

    grid_barrier(local_sense);

    // ================= PHASE 4 =================
    // blocks 0..127: score (warp per (n,k), v[n] staged in smem, f4 dot)
    // blocks 128..131: gather R4
    if (b < 128) {
        const int n = b >> 2;                       // constant per block
        // stage v[n] (768 floats) into smem
        for (int i = tid; i < H; i += THREADS) sm[i] = g_v[n * H + i];
        __syncthreads();

        const int k = 8 * (b & 3) + wid;            // 0..31
        const float4* p4 = (const float4*)(pool1 + (size_t)(n * KK + k) * H);
        const float4* v4 = (const float4*)sm;
        float a = 0.f;
#pragma unroll
        for (int i = 0; i < 6; i++) {
            float4 p = p4[lane + 32 * i];
            float4 v = v4[lane + 32 * i];
            a += p.x * v.x + p.y * v.y + p.z * v.z + p.w * v.w;
        }
#pragma unroll
        for (int o = 16; o > 0; o >>= 1) a += __shfl_xor_sync(0xffffffffu, a, o);
        if (lane == 0)
            out[OFF_SCORE + n * KK + k] =
                (ckmask[n * KK + k] != 0) ? (a + g_c[n]) : NEGINF;
    } else {
        gather_range(p0f4, label, outE4, R4_LO, R4_HI,
                     (b - 128) * THREADS + tid, 4 * THREADS);
    }

    // ================= POST (no barrier needed) =================
    // small outputs + remaining gather, all threads
    {
        int gt = b * THREADS + tid;                 // < 33792
        if (gt < 4096) {
            int n = gt >> 7, t = gt & 127;
            out[OFF_MASK + gt] =
                (pmask[(n * KK + label[n]) * TT + t] != 0) ? 1.f : 0.f;
        } else if (gt < 4096 + 24576) {
            int j = gt - 4096;
            int n = j / H, h2 = j - n * H;
            out[OFF_USE + j] = pool1[(size_t)(n * KK + label[n]) * H + h2];
        } else if (gt < 4096 + 24576 + 4096) {
            int j = gt - 4096 - 24576;
            int n = j >> 7, t = j & 127;
            out[OFF_IDX + j] = (float)ptok[(n * KK + label[n]) * TT + t];
        }
        gather_range(p0f4, label, outE4, R5_LO, R5_HI, gt, GRID * THREADS);
    }
}

extern "C" void kernel_launch(void* const* d_in, const int* in_sizes, int n_in,
                              void* d_out, int out_size) {
    const float* ctx     = (const float*)d_in[0];   // (32,3,768)
    const float* tracked = (const float*)d_in[1];   // (32,768)
    const float* pool0   = (const float*)d_in[2];   // (32,32,128,768)
    const float* pool1   = (const float*)d_in[3];   // (32,32,768)
    const int*   pmask   = (const int*)d_in[4];     // (32,32,128) bool->4B
    const int*   ckmask  = (const int*)d_in[5];     // (32,32)     bool->4B
    const int*   label   = (const int*)d_in[6];     // (32,)
    const int*   ptok    = (const int*)d_in[7];     // (32,32,128)
    const float* Wcqk    = (const float*)d_in[8];   // (768,1536)
    const float* bcqk    = (const float*)d_in[9];   // (768,)
    const float* Wk      = (const float*)d_in[10];  // (768,768)
    const float* bk      = (const float*)d_in[11];  // (768,)
    float* out = (float*)d_out;

    fused_kernel<<<GRID, THREADS>>>(ctx, tracked, pool0, pool1, pmask, ckmask,
                                    label, ptok, Wcqk, bcqk, Wk, bk, out);
}